// round 1
// baseline (speedup 1.0000x reference)
#include <cuda_runtime.h>
#include <math.h>

// Kalman filter one-step-ahead predictions.
// B=512 groups, T=256 steps, S=32 state dim, M=4 measurement dim.
// One block of 64 threads per batch element; state kept in shared memory
// across the sequential time loop.
//
// Inputs (metadata order):
//  d_in[0] input     [B,T,M]   f32
//  d_in[1] F         [S,S]     f32
//  d_in[2] Q         [S,S]     f32
//  d_in[3] H         [M,S]     f32
//  d_in[4] R         [M,M]     f32
//  d_in[5] init_mean [B,S]     f32
//  d_in[6] init_cov  [B,S,S]   f32
// Output: meas_means [T,B,M] followed by meas_covs [T,B,M,M], f32.

#define Sdim 32
#define Mdim 4
#define Tsteps 256
#define Bn 512
#define LD 33  // padded leading dim for 32-wide shared arrays

__global__ __launch_bounds__(64) void kalman_kernel(
    const float* __restrict__ obs,      // [B,T,M]
    const float* __restrict__ Fm,       // [S,S]
    const float* __restrict__ Qm,       // [S,S]
    const float* __restrict__ Hm,       // [M,S]
    const float* __restrict__ Rm,       // [M,M]
    const float* __restrict__ init_mean,// [B,S]
    const float* __restrict__ init_cov, // [B,S,S]
    float* __restrict__ out)            // means then covs
{
    const int b   = blockIdx.x;
    const int tid = threadIdx.x;

    __shared__ float sF [Sdim * LD];   // F[i][k]
    __shared__ float sFT[Sdim * LD];   // F^T[k][j] = F[j][k]
    __shared__ float sQ [Sdim * LD];
    __shared__ float sP [Sdim * LD];   // covariance (prediction)
    __shared__ float sW [Sdim * LD];   // W = P_u * F^T
    __shared__ float sH [Mdim * LD];   // H[m][k]
    __shared__ float sPHtT[Mdim * LD]; // (P H^T)^T : [m][i]
    __shared__ float sKT  [Mdim * LD]; // K^T : [m][i]
    __shared__ float sR[16];
    __shared__ float sS[16];           // innovation covariance
    __shared__ float sL[16];           // cholesky factor (lower)
    __shared__ float sInvD[4];
    __shared__ float sm[Sdim];         // mean (prediction)
    __shared__ float smn[Sdim];        // next mean scratch
    __shared__ float smm[Mdim];        // measurement mean
    __shared__ float sresid[Mdim];

    // ---- load constants + per-batch initial state ----
    for (int idx = tid; idx < Sdim * Sdim; idx += 64) {
        int i = idx >> 5, k = idx & 31;
        float f = Fm[idx];
        sF [i * LD + k] = f;
        sFT[k * LD + i] = f;
        sQ [i * LD + k] = Qm[idx];
        sP [i * LD + k] = init_cov[(size_t)b * (Sdim * Sdim) + idx];
    }
    for (int idx = tid; idx < Mdim * Sdim; idx += 64) {
        int m = idx >> 5, k = idx & 31;
        sH[m * LD + k] = Hm[idx];
    }
    if (tid < 16) sR[tid] = Rm[tid];
    if (tid < 32) sm[tid] = init_mean[b * Sdim + tid];
    __syncthreads();

    const float* yb = obs + (size_t)b * (Tsteps * Mdim);
    float* out_means = out;                                  // [T,B,M]
    float* out_covs  = out + (size_t)Tsteps * Bn * Mdim;     // [T,B,M,M]

#pragma unroll 1
    for (int t = 0; t < Tsteps; ++t) {
        // ---- Phase 1: PHtT[m][i] = sum_k P[i][k] * H[m][k]  (2 outputs/thread)
        {
            int i  = tid & 31;
            int m0 = tid >> 5;  // 0 or 1 -> handles m0 and m0+2
            float acc0 = 0.f, acc2 = 0.f;
#pragma unroll
            for (int k = 0; k < Sdim; ++k) {
                float p = sP[i * LD + k];
                acc0 += p * sH[m0 * LD + k];
                acc2 += p * sH[(m0 + 2) * LD + k];
            }
            sPHtT[m0 * LD + i]       = acc0;
            sPHtT[(m0 + 2) * LD + i] = acc2;
        }
        // measurement mean mm = H * m (threads 0..3)
        if (tid < 4) {
            float acc = 0.f;
#pragma unroll
            for (int k = 0; k < Sdim; ++k) acc += sH[tid * LD + k] * sm[k];
            smm[tid] = acc;
        }
        __syncthreads();

        // ---- Phase 2: S = H*PHt + R (threads 0..15), emit outputs, residual
        if (tid < 16) {
            int m = tid >> 2, n = tid & 3;
            float acc = sR[tid];
#pragma unroll
            for (int k = 0; k < Sdim; ++k)
                acc += sH[m * LD + k] * sPHtT[n * LD + k];
            sS[tid] = acc;
            out_covs[((size_t)t * Bn + b) * 16 + tid] = acc;  // mc_t == S_t
        } else if (tid < 20) {
            int m = tid - 16;
            float mmv = smm[m];
            sresid[m] = yb[t * Mdim + m] - mmv;
            out_means[((size_t)t * Bn + b) * Mdim + m] = mmv;
        }
        __syncthreads();

        if (t == Tsteps - 1) break;  // last step only emits

        // ---- Phase 3: 4x4 Cholesky of S (thread 0)
        if (tid == 0) {
            float a00 = sS[0];
            float a10 = sS[4],  a11 = sS[5];
            float a20 = sS[8],  a21 = sS[9],  a22 = sS[10];
            float a30 = sS[12], a31 = sS[13], a32 = sS[14], a33 = sS[15];
            float l00 = sqrtf(a00),  i0 = 1.f / l00;
            float l10 = a10 * i0, l20 = a20 * i0, l30 = a30 * i0;
            float l11 = sqrtf(a11 - l10 * l10), i1 = 1.f / l11;
            float l21 = (a21 - l20 * l10) * i1;
            float l31 = (a31 - l30 * l10) * i1;
            float l22 = sqrtf(a22 - l20 * l20 - l21 * l21), i2 = 1.f / l22;
            float l32 = (a32 - l30 * l20 - l31 * l21) * i2;
            float l33 = sqrtf(a33 - l30 * l30 - l31 * l31 - l32 * l32);
            float i3 = 1.f / l33;
            sL[4] = l10; sL[8] = l20; sL[9] = l21;
            sL[12] = l30; sL[13] = l31; sL[14] = l32;
            sInvD[0] = i0; sInvD[1] = i1; sInvD[2] = i2; sInvD[3] = i3;
        }
        __syncthreads();

        // ---- Phase 4: solve S * KT = PHtT per column (threads 0..31)
        if (tid < 32) {
            int i = tid;
            float r0 = sPHtT[0 * LD + i], r1 = sPHtT[1 * LD + i];
            float r2 = sPHtT[2 * LD + i], r3 = sPHtT[3 * LD + i];
            float i0 = sInvD[0], i1 = sInvD[1], i2 = sInvD[2], i3 = sInvD[3];
            float L10 = sL[4],  L20 = sL[8],  L21 = sL[9];
            float L30 = sL[12], L31 = sL[13], L32 = sL[14];
            float z0 = r0 * i0;
            float z1 = (r1 - L10 * z0) * i1;
            float z2 = (r2 - L20 * z0 - L21 * z1) * i2;
            float z3 = (r3 - L30 * z0 - L31 * z1 - L32 * z2) * i3;
            float x3 = z3 * i3;
            float x2 = (z2 - L32 * x3) * i2;
            float x1 = (z1 - L21 * x2 - L31 * x3) * i1;
            float x0 = (z0 - L10 * x1 - L20 * x2 - L30 * x3) * i0;
            sKT[0 * LD + i] = x0; sKT[1 * LD + i] = x1;
            sKT[2 * LD + i] = x2; sKT[3 * LD + i] = x3;
        }
        __syncthreads();

        // ---- Phase 5: P_u = P - K * PHt^T  (rank-4 downdate), m_u = m + K*resid
        {
            int j = tid & 31;
            int ibase = tid >> 5;
            float k0j = sPHtT[0 * LD + j], k1j = sPHtT[1 * LD + j];
            float k2j = sPHtT[2 * LD + j], k3j = sPHtT[3 * LD + j];
#pragma unroll
            for (int r = 0; r < 16; ++r) {
                int i = ibase + 2 * r;
                float v = sP[i * LD + j];
                v -= sKT[0 * LD + i] * k0j + sKT[1 * LD + i] * k1j
                   + sKT[2 * LD + i] * k2j + sKT[3 * LD + i] * k3j;
                sP[i * LD + j] = v;
            }
        }
        if (tid >= 32) {
            int i = tid - 32;
            sm[i] += sKT[0 * LD + i] * sresid[0] + sKT[1 * LD + i] * sresid[1]
                   + sKT[2 * LD + i] * sresid[2] + sKT[3 * LD + i] * sresid[3];
        }
        __syncthreads();

        // ---- Phase 6: W = P_u * F^T   (4x4 register tiles, 16 outputs/thread)
        {
            int jc = tid & 7, j0 = jc * 4;
            int ir = tid >> 3;  // 0..7
            float acc[4][4];
#pragma unroll
            for (int r = 0; r < 4; ++r)
#pragma unroll
                for (int c = 0; c < 4; ++c) acc[r][c] = 0.f;
#pragma unroll
            for (int k = 0; k < Sdim; ++k) {
                float b0 = sFT[k * LD + j0 + 0];
                float b1 = sFT[k * LD + j0 + 1];
                float b2 = sFT[k * LD + j0 + 2];
                float b3 = sFT[k * LD + j0 + 3];
#pragma unroll
                for (int r = 0; r < 4; ++r) {
                    float a = sP[(ir + 8 * r) * LD + k];
                    acc[r][0] += a * b0; acc[r][1] += a * b1;
                    acc[r][2] += a * b2; acc[r][3] += a * b3;
                }
            }
#pragma unroll
            for (int r = 0; r < 4; ++r) {
                int i = ir + 8 * r;
                sW[i * LD + j0 + 0] = acc[r][0];
                sW[i * LD + j0 + 1] = acc[r][1];
                sW[i * LD + j0 + 2] = acc[r][2];
                sW[i * LD + j0 + 3] = acc[r][3];
            }
        }
        // m_p = F * m_u (threads 0..31, after their GEMM tile)
        if (tid < 32) {
            float acc = 0.f;
#pragma unroll
            for (int k = 0; k < Sdim; ++k) acc += sF[tid * LD + k] * sm[k];
            smn[tid] = acc;
        }
        __syncthreads();

        // ---- Phase 7: P = F * W + Q ; commit mean
        {
            int jc = tid & 7, j0 = jc * 4;
            int ir = tid >> 3;
            float acc[4][4];
#pragma unroll
            for (int r = 0; r < 4; ++r) {
                int i = ir + 8 * r;
                acc[r][0] = sQ[i * LD + j0 + 0];
                acc[r][1] = sQ[i * LD + j0 + 1];
                acc[r][2] = sQ[i * LD + j0 + 2];
                acc[r][3] = sQ[i * LD + j0 + 3];
            }
#pragma unroll
            for (int k = 0; k < Sdim; ++k) {
                float b0 = sW[k * LD + j0 + 0];
                float b1 = sW[k * LD + j0 + 1];
                float b2 = sW[k * LD + j0 + 2];
                float b3 = sW[k * LD + j0 + 3];
#pragma unroll
                for (int r = 0; r < 4; ++r) {
                    float a = sF[(ir + 8 * r) * LD + k];
                    acc[r][0] += a * b0; acc[r][1] += a * b1;
                    acc[r][2] += a * b2; acc[r][3] += a * b3;
                }
            }
#pragma unroll
            for (int r = 0; r < 4; ++r) {
                int i = ir + 8 * r;
                sP[i * LD + j0 + 0] = acc[r][0];
                sP[i * LD + j0 + 1] = acc[r][1];
                sP[i * LD + j0 + 2] = acc[r][2];
                sP[i * LD + j0 + 3] = acc[r][3];
            }
        }
        if (tid >= 32) sm[tid - 32] = smn[tid - 32];
        __syncthreads();
    }
}

extern "C" void kernel_launch(void* const* d_in, const int* in_sizes, int n_in,
                              void* d_out, int out_size)
{
    const float* obs       = (const float*)d_in[0];
    const float* Fm        = (const float*)d_in[1];
    const float* Qm        = (const float*)d_in[2];
    const float* Hm        = (const float*)d_in[3];
    const float* Rm        = (const float*)d_in[4];
    const float* init_mean = (const float*)d_in[5];
    const float* init_cov  = (const float*)d_in[6];
    float* out = (float*)d_out;

    kalman_kernel<<<Bn, 64>>>(obs, Fm, Qm, Hm, Rm, init_mean, init_cov, out);
}

// round 2
// speedup vs baseline: 1.2057x; 1.2057x over previous
#include <cuda_runtime.h>
#include <math.h>

// Kalman filter one-step-ahead predictions, warp-per-batch, register-resident P.
// B=512, T=256, S=32, M=4.
// Lane j of each warp holds column j (== row j, symmetric) of the 32x32
// covariance in registers. F (packed pairs), Q (packed column pairs), H are in
// shared; GEMM inner products use packed fma.rn.f32x2 with uniform-broadcast
// LDS.128 reads of F. One shared round-trip per step for the X = P_u*F^T
// intermediate (transpose). No __syncthreads; warp-synchronous only.

#define Bn 512
#define Tn 256
#define Sn 32
#define Mn 4

using u64 = unsigned long long;

__device__ __forceinline__ u64 pack2(float lo, float hi) {
    u64 r; asm("mov.b64 %0,{%1,%2};" : "=l"(r) : "f"(lo), "f"(hi)); return r;
}
__device__ __forceinline__ void unpack2(u64 v, float& lo, float& hi) {
    asm("mov.b64 {%0,%1},%2;" : "=f"(lo), "=f"(hi) : "l"(v));
}
__device__ __forceinline__ u64 ffma2(u64 a, u64 b, u64 c) {
    u64 d; asm("fma.rn.f32x2 %0,%1,%2,%3;" : "=l"(d) : "l"(a), "l"(b), "l"(c)); return d;
}

__global__ __launch_bounds__(32) void kalman_kernel(
    const float* __restrict__ obs,       // [B,T,M]
    const float* __restrict__ Fm,        // [S,S]
    const float* __restrict__ Qm,        // [S,S]
    const float* __restrict__ Hm,        // [M,S]
    const float* __restrict__ Rm,        // [M,M]
    const float* __restrict__ init_mean, // [B,S]
    const float* __restrict__ init_cov,  // [B,S,S]
    float* __restrict__ out)
{
    const int b    = blockIdx.x;
    const int lane = threadIdx.x;

    // F pairs: float view fview[l*36 + i] = F[i][l]; u64 view [l*18 + c] = (F[2c][l],F[2c+1][l])
    __shared__ __align__(16) u64 sFTp[Sn * 18];
    // Q column pairs: float view [j*36 + i] = Q[i][j]
    __shared__ __align__(16) u64 sQp[Sn * 18];
    // H: float view [l*4 + q] = H[q][l]
    __shared__ __align__(16) u64 sHTp[Sn * 2];
    // PH^T rows: float view [l*4 + r] = phtt_l[r]
    __shared__ __align__(16) u64 sPHp[Sn * 2];
    // X = P_u * F^T, rows; padded to 36 floats per row
    __shared__ __align__(16) float sX[Sn * 36];
    // whitened vectors z per row
    __shared__ __align__(16) float sZ[Sn * 4];
    __shared__ float sR16[16];

    {
        float* fv = (float*)sFTp;
        float* qv = (float*)sQp;
        for (int idx = lane; idx < Sn * Sn; idx += 32) {
            int i = idx >> 5, l = idx & 31;
            fv[l * 36 + i] = Fm[idx];        // F[i][l]
            qv[l * 36 + i] = Qm[idx];        // here: Q[i][l] -> column l pairs over i
        }
        float* hv = (float*)sHTp;
        for (int idx = lane; idx < Mn * Sn; idx += 32) {
            int q = idx >> 5, l = idx & 31;
            hv[l * 4 + q] = Hm[idx];
        }
        if (lane < 16) sR16[lane] = Rm[lane];
    }

    // per-lane state: P column `lane`, mean element `lane`, H column `lane`
    float p[Sn];
#pragma unroll
    for (int i = 0; i < Sn; ++i)
        p[i] = init_cov[(size_t)b * (Sn * Sn) + i * Sn + lane];
    float mloc = init_mean[b * Sn + lane];
    float Hl0 = Hm[0 * Sn + lane], Hl1 = Hm[1 * Sn + lane];
    float Hl2 = Hm[2 * Sn + lane], Hl3 = Hm[3 * Sn + lane];
    __syncwarp();

    const float* yb = obs + (size_t)b * (Tn * Mn);
    float* out_means = out;                               // [T,B,M]
    float* out_covs  = out + (size_t)Tn * Bn * Mn;        // [T,B,M,M]

    float4 yn = *(const float4*)yb;  // prefetch y_0

#pragma unroll 1
    for (int t = 0; t < Tn; ++t) {
        float4 yv = yn;
        int tnext = (t + 1 < Tn) ? (t + 1) : (Tn - 1);
        yn = *(const float4*)(yb + 4 * tnext);

        // ---- measurement mean mm = H * m (butterfly reduce, all lanes get it)
        float c0 = Hl0 * mloc, c1 = Hl1 * mloc, c2 = Hl2 * mloc, c3 = Hl3 * mloc;
#pragma unroll
        for (int s = 16; s >= 1; s >>= 1) {
            c0 += __shfl_xor_sync(0xffffffffu, c0, s);
            c1 += __shfl_xor_sync(0xffffffffu, c1, s);
            c2 += __shfl_xor_sync(0xffffffffu, c2, s);
            c3 += __shfl_xor_sync(0xffffffffu, c3, s);
        }
        if (lane == 0)
            *(float4*)&out_means[((size_t)t * Bn + b) * 4] = make_float4(c0, c1, c2, c3);
        float r0 = yv.x - c0, r1 = yv.y - c1, r2 = yv.z - c2, r3 = yv.w - c3;

        // ---- phtt = row `lane` of P*H^T  (packed f32x2)
        u64 ph2a = 0ull, ph2b = 0ull;
#pragma unroll
        for (int l = 0; l < Sn; ++l) {
            u64 ps = pack2(p[l], p[l]);
            ulonglong2 h = *(const ulonglong2*)&sHTp[l * 2];
            ph2a = ffma2(ps, h.x, ph2a);
            ph2b = ffma2(ps, h.y, ph2b);
        }
        float ph0, ph1, phh2, ph3;
        unpack2(ph2a, ph0, ph1);
        unpack2(ph2b, phh2, ph3);
        sPHp[lane * 2 + 0] = ph2a;
        sPHp[lane * 2 + 1] = ph2b;
        __syncwarp();

        // ---- S = H*(PH^T) + R : lane (q,r) = lane index q*4+r (dup for lanes>=16)
        int q = (lane >> 2) & 3, r = lane & 3;
        float sv = sR16[(q << 2) | r];
        {
            const float* hf = (const float*)sHTp;
            const float* pf = (const float*)sPHp;
#pragma unroll 8
            for (int l = 0; l < Sn; ++l)
                sv = fmaf(hf[l * 4 + q], pf[l * 4 + r], sv);
        }
        if (lane < 16)
            out_covs[((size_t)t * Bn + b) * 16 + lane] = sv;  // mc_t == S_t

        if (t == Tn - 1) break;

        // ---- broadcast S, 4x4 Cholesky (all lanes, redundant)
        float s00 = __shfl_sync(0xffffffffu, sv, 0);
        float s10 = __shfl_sync(0xffffffffu, sv, 4);
        float s11 = __shfl_sync(0xffffffffu, sv, 5);
        float s20 = __shfl_sync(0xffffffffu, sv, 8);
        float s21 = __shfl_sync(0xffffffffu, sv, 9);
        float s22 = __shfl_sync(0xffffffffu, sv, 10);
        float s30 = __shfl_sync(0xffffffffu, sv, 12);
        float s31 = __shfl_sync(0xffffffffu, sv, 13);
        float s32 = __shfl_sync(0xffffffffu, sv, 14);
        float s33 = __shfl_sync(0xffffffffu, sv, 15);
        float l00 = sqrtf(s00), i0 = 1.f / l00;
        float L10 = s10 * i0, L20 = s20 * i0, L30 = s30 * i0;
        float l11 = sqrtf(s11 - L10 * L10), i1 = 1.f / l11;
        float L21 = (s21 - L20 * L10) * i1;
        float L31 = (s31 - L30 * L10) * i1;
        float l22 = sqrtf(s22 - L20 * L20 - L21 * L21), i2 = 1.f / l22;
        float L32 = (s32 - L30 * L20 - L31 * L21) * i2;
        float l33 = sqrtf(s33 - L30 * L30 - L31 * L31 - L32 * L32), i3 = 1.f / l33;

        // ---- whitened z (forward solve) and gain row k (back solve), per lane
        float z0 = ph0 * i0;
        float z1 = (ph1 - L10 * z0) * i1;
        float z2 = (phh2 - L20 * z0 - L21 * z1) * i2;
        float z3 = (ph3 - L30 * z0 - L31 * z1 - L32 * z2) * i3;
        float k3 = z3 * i3;
        float k2 = (z2 - L32 * k3) * i2;
        float k1 = (z1 - L21 * k2 - L31 * k3) * i1;
        float k0 = (z0 - L10 * k1 - L20 * k2 - L30 * k3) * i0;

        *(float4*)&sZ[lane * 4] = make_float4(z0, z1, z2, z3);
        __syncwarp();

        // ---- mean update
        mloc = fmaf(k0, r0, fmaf(k1, r1, fmaf(k2, r2, fmaf(k3, r3, mloc))));

        // ---- covariance downdate: p[i] -= z_i . z_lane  (bitwise symmetric)
#pragma unroll
        for (int i = 0; i < Sn; ++i) {
            float4 zi = *(const float4*)&sZ[i * 4];
            float d = zi.x * z0;
            d = fmaf(zi.y, z1, d);
            d = fmaf(zi.z, z2, d);
            d = fmaf(zi.w, z3, d);
            p[i] -= d;
        }

        // ---- GEMM1: X row `lane` = p (row of P_u) times F^T : x[m] = sum_l p[l]*F[m][l]
        u64 x2[16];
#pragma unroll
        for (int c = 0; c < 16; ++c) x2[c] = 0ull;
#pragma unroll
        for (int l = 0; l < Sn; ++l) {
            u64 ps = pack2(p[l], p[l]);
            const ulonglong2* fr = (const ulonglong2*)&sFTp[l * 18];
#pragma unroll
            for (int c2 = 0; c2 < 8; ++c2) {
                ulonglong2 f = fr[c2];
                x2[2 * c2 + 0] = ffma2(ps, f.x, x2[2 * c2 + 0]);
                x2[2 * c2 + 1] = ffma2(ps, f.y, x2[2 * c2 + 1]);
            }
        }
#pragma unroll
        for (int c = 0; c < 16; ++c)
            *(u64*)&sX[lane * 36 + 2 * c] = x2[c];
        __syncwarp();

        // ---- mean predict: mp[lane] = sum_l F[lane][l] * m_u[l]
        float mp = 0.f;
        {
            const float* fv = (const float*)sFTp;
#pragma unroll 8
            for (int l = 0; l < Sn; ++l) {
                float ml = __shfl_sync(0xffffffffu, mloc, l);
                mp = fmaf(fv[l * 36 + lane], ml, mp);
            }
        }

        // ---- GEMM2: P_new column `lane` = F * X[:,lane] + Q[:,lane]
        u64 a2[16];
        {
            const ulonglong2* qr = (const ulonglong2*)&sQp[lane * 18];
#pragma unroll
            for (int c2 = 0; c2 < 8; ++c2) {
                ulonglong2 qq = qr[c2];
                a2[2 * c2 + 0] = qq.x;
                a2[2 * c2 + 1] = qq.y;
            }
        }
#pragma unroll 4
        for (int k = 0; k < Sn; ++k) {
            float xv = sX[k * 36 + lane];
            u64 xs = pack2(xv, xv);
            const ulonglong2* fr = (const ulonglong2*)&sFTp[k * 18];
#pragma unroll
            for (int c2 = 0; c2 < 8; ++c2) {
                ulonglong2 f = fr[c2];
                a2[2 * c2 + 0] = ffma2(xs, f.x, a2[2 * c2 + 0]);
                a2[2 * c2 + 1] = ffma2(xs, f.y, a2[2 * c2 + 1]);
            }
        }
#pragma unroll
        for (int c = 0; c < 16; ++c)
            unpack2(a2[c], p[2 * c], p[2 * c + 1]);

        mloc = mp;
        __syncwarp();
    }
}

extern "C" void kernel_launch(void* const* d_in, const int* in_sizes, int n_in,
                              void* d_out, int out_size)
{
    const float* obs       = (const float*)d_in[0];
    const float* Fm        = (const float*)d_in[1];
    const float* Qm        = (const float*)d_in[2];
    const float* Hm        = (const float*)d_in[3];
    const float* Rm        = (const float*)d_in[4];
    const float* init_mean = (const float*)d_in[5];
    const float* init_cov  = (const float*)d_in[6];
    float* out = (float*)d_out;

    kalman_kernel<<<Bn, 32>>>(obs, Fm, Qm, Hm, Rm, init_mean, init_cov, out);
}